// round 8
// baseline (speedup 1.0000x reference)
#include <cuda_runtime.h>
#include <math.h>

// x:[32,512,56,56] f32, w1:[32,512], w2:[512,32]
// out = concat(scaled [32,512,56,56], comp [32,512])

#define B 32
#define C 512
#define CR 32
#define HW 3136
#define HW4 784
#define BC (B*C)            // 16384
#define NTOT (B*C*HW)
#define N4 (NTOT/4)         // 12845056 float4s
#define HALF4 (N4/2)        // 6422528 (= 8192*784, channel-aligned)

#define NBLOCKS 592                 // 148 SMs x 4 resident blocks (GB300 has 152 -> safe)
#define NTHREADS (NBLOCKS*256)      // 151552
#define NWARPS (NBLOCKS*8)          // 4736

__device__ float g_y[BC];
__device__ float g_gate[BC];
__device__ unsigned long long g_bar;   // monotonic ticket counter (zero-init)

// Grid-wide barrier, replay-safe: each launch adds exactly 2*NBLOCKS tickets,
// so the counter stays a multiple of NBLOCKS at launch boundaries.
__device__ __forceinline__ void grid_barrier() {
    __syncthreads();
    if (threadIdx.x == 0) {
        __threadfence();  // publish this block's prior writes (gpu scope)
        unsigned long long ticket = atomicAdd(&g_bar, 1ULL);
        unsigned long long target = (ticket / NBLOCKS + 1ULL) * (unsigned long long)NBLOCKS;
        unsigned long long v;
        do {
            asm volatile("ld.global.acquire.gpu.u64 %0, [%1];" : "=l"(v) : "l"(&g_bar));
        } while (v < target);
    }
    __syncthreads();
}

// ---------------------------------------------------------------------------
// Single persistent kernel: reduce -> barrier -> MLP -> barrier -> apply.
// ---------------------------------------------------------------------------
__global__ void __launch_bounds__(256, 4)
se_fused(const float* __restrict__ x,
         const float* __restrict__ w1,
         const float* __restrict__ w2,
         float* __restrict__ out) {
    const int tid  = threadIdx.x;
    const int warp = tid >> 5;
    const int lane = tid & 31;
    const float4* __restrict__ xp4 = reinterpret_cast<const float4*>(x);

    // ---- Phase 1: y[bc] = mean(x[bc,:]), one warp per channel, grid-stride.
    for (int bc = blockIdx.x * 8 + warp; bc < BC; bc += NWARPS) {
        const float4* __restrict__ xp = xp4 + (size_t)bc * HW4;
        float s = 0.f;
        int j = lane;
        #pragma unroll 6
        for (int k = 0; k < 24; k++, j += 32) {
            float4 v = __ldcs(&xp[j]);
            s += (v.x + v.y) + (v.z + v.w);
        }
        if (lane < 16) {                   // 784 = 24*32 + 16
            float4 v = __ldcs(&xp[768 + lane]);
            s += (v.x + v.y) + (v.z + v.w);
        }
        #pragma unroll
        for (int o = 16; o > 0; o >>= 1)
            s += __shfl_xor_sync(0xFFFFFFFFu, s, o);
        if (lane == 0) g_y[bc] = s * (1.0f / HW);
    }

    grid_barrier();

    // ---- Phase 2: MLP + comp, blocks 0..31 only (one per batch).
    if (blockIdx.x < B) {
        __shared__ float y_s[C];
        __shared__ float h_s[CR];
        const int b = blockIdx.x;

        y_s[tid]       = g_y[b * C + tid];
        y_s[tid + 256] = g_y[b * C + tid + 256];
        __syncthreads();

        // h[r] = relu(sum_c y[c]*w1[r][c]); 8 warps x 4 r's each.
        #pragma unroll
        for (int r4 = 0; r4 < 4; r4++) {
            const int r = warp * 4 + r4;
            const float* __restrict__ w1r = w1 + r * C;
            float acc = 0.f;
            #pragma unroll
            for (int c = lane; c < C; c += 32)
                acc += y_s[c] * w1r[c];
            #pragma unroll
            for (int o = 16; o > 0; o >>= 1)
                acc += __shfl_xor_sync(0xFFFFFFFFu, acc, o);
            if (lane == 0) h_s[r] = fmaxf(acc, 0.f);
        }
        __syncthreads();

        // g[c] = sigmoid(h . w2[c]); comp = y*(1-g). Two c's per thread.
        float* comp = out + NTOT;
        #pragma unroll
        for (int cc = 0; cc < 2; cc++) {
            const int c = tid + cc * 256;
            const float4* __restrict__ w2c = reinterpret_cast<const float4*>(w2 + c * CR);
            float acc = 0.f;
            #pragma unroll
            for (int j = 0; j < 8; j++) {
                float4 w = w2c[j];
                acc += h_s[4*j+0]*w.x + h_s[4*j+1]*w.y + h_s[4*j+2]*w.z + h_s[4*j+3]*w.w;
            }
            const float g = 1.0f / (1.0f + expf(-acc));
            const int idx = b * C + c;
            g_gate[idx] = g;
            comp[idx] = y_s[c] * (1.0f - g);
        }
    }

    grid_barrier();

    // ---- Phase 3: scaled = x * gate. Two distant coalesced streams per
    // thread (i, i+HALF4), grid-stride. Plain gate loads (coherent after
    // acquire barrier). Streaming hints on x/out.
    float4* __restrict__ op = reinterpret_cast<float4*>(out);
    for (int t = blockIdx.x * 256 + tid; t < HALF4; t += NTHREADS) {
        const int i1 = t + HALF4;
        const float g0 = g_gate[t  / HW4];
        const float g1 = g_gate[i1 / HW4];
        float4 v0 = __ldcs(&xp4[t]);
        float4 v1 = __ldcs(&xp4[i1]);
        v0.x *= g0; v0.y *= g0; v0.z *= g0; v0.w *= g0;
        v1.x *= g1; v1.y *= g1; v1.z *= g1; v1.w *= g1;
        __stcs(&op[t],  v0);
        __stcs(&op[i1], v1);
    }
}

// ---------------------------------------------------------------------------
extern "C" void kernel_launch(void* const* d_in, const int* in_sizes, int n_in,
                              void* d_out, int out_size) {
    const float* x  = (const float*)d_in[0];
    const float* w1 = (const float*)d_in[1];
    const float* w2 = (const float*)d_in[2];
    float* out = (float*)d_out;

    se_fused<<<NBLOCKS, 256>>>(x, w1, w2, out);
}